// round 10
// baseline (speedup 1.0000x reference)
#include <cuda_runtime.h>
#include <cuda_bf16.h>
#include <cstdint>

// SDFVae per-part MLP on mma.sync.m16n8k16 (bf16 hi+mid split, f32 accum).
// R10: term-major MMA issue (4 independent C-chains), L1/L2 B-frag tables in
// smem (frees ~64 regs), __launch_bounds__(128,4) -> 16 warps/SM.
//   d_in[0] points [8,42,16384,3] f32   d_in[1] features [8,336] f32
//   d_in[2] W0 [42,32,17]  d_in[3] W1 [42,32,32]
//   d_in[4] W2 [42,32,32]  d_in[5] W3 [42,1,32]
//   out [8,16384,42] f32

#define B_ 8
#define P_ 42
#define N_ 16384
#define THREADS 128
#define CHUNK 2048
#define ITERS (CHUNK / 128)   // 16

__device__ __forceinline__ void mma16816(float c[4],
    uint32_t a0, uint32_t a1, uint32_t a2, uint32_t a3,
    uint32_t b0, uint32_t b1)
{
    asm volatile(
        "mma.sync.aligned.m16n8k16.row.col.f32.bf16.bf16.f32 "
        "{%0,%1,%2,%3}, {%4,%5,%6,%7}, {%8,%9}, {%0,%1,%2,%3};"
        : "+f"(c[0]), "+f"(c[1]), "+f"(c[2]), "+f"(c[3])
        : "r"(a0), "r"(a1), "r"(a2), "r"(a3), "r"(b0), "r"(b1));
}
__device__ __forceinline__ uint32_t pack_rn(float lo, float hi) {
    uint32_t r;
    asm("cvt.rn.satfinite.bf16x2.f32 %0, %1, %2;" : "=r"(r) : "f"(hi), "f"(lo));
    return r;
}
__device__ __forceinline__ uint32_t pack_hi16(float lo, float hi) {
    return __byte_perm(__float_as_uint(lo), __float_as_uint(hi), 0x7632);
}
__device__ __forceinline__ float trunc_bf(float v) {
    return __uint_as_float(__float_as_uint(v) & 0xFFFF0000u);
}
__device__ __forceinline__ float rn_bf(float v) {
    return __bfloat162float(__float2bfloat16(v));
}

// issue 4 independent n-chains for one (A, B-quad-pair) term
#define MMA_T4(C, Ak, q0, q1) do { \
    mma16816((C)[0], (Ak)[0], (Ak)[1], (Ak)[2], (Ak)[3], (q0).x, (q1).x); \
    mma16816((C)[1], (Ak)[0], (Ak)[1], (Ak)[2], (Ak)[3], (q0).y, (q1).y); \
    mma16816((C)[2], (Ak)[0], (Ak)[1], (Ak)[2], (Ak)[3], (q0).z, (q1).z); \
    mma16816((C)[3], (Ak)[0], (Ak)[1], (Ak)[2], (Ak)[3], (q0).w, (q1).w); \
} while (0)

__global__ __launch_bounds__(THREADS, 4)
void sdfvae_mma_kernel(const float* __restrict__ points,
                       const float* __restrict__ features,
                       const float* __restrict__ W0,
                       const float* __restrict__ W1,
                       const float* __restrict__ W2,
                       const float* __restrict__ W3,
                       float* __restrict__ out)
{
    const int chunk = blockIdx.x, p = blockIdx.y, b = blockIdx.z;
    const int tid = threadIdx.x;
    const int w = tid >> 5, lane = tid & 31;
    const int g = lane >> 2, q = lane & 3;

    // per-warp pe staging: [warp][row][pair]
    __shared__ uint32_t sPEh[4][32][9];
    __shared__ uint32_t sPEm[4][32][9];
    // B-frag tables, identical for all warps: [lane][frag], pad 36 for
    // conflict-free LDS.128 (4*lane mod 32 start banks).
    // frag f: [0..15] hi: f = kb*8 + r*4 + ntile ; [16..31] mid (same order)
    __shared__ uint32_t sB1[32][36];
    __shared__ uint32_t sB2[32][36];

    // ---- per-thread L0 + L3 fragments (regs) ----
    uint32_t b0h[4][2], b0m[4][2];
    float    w3r[4][2];

    const float* W0p = W0 + p * 32 * 17;
    const float* fv  = features + (b * P_ + p) * 8;

    #pragma unroll
    for (int j = 0; j < 4; j++) {
        const int n = g + 8 * j;
        const float* w0r = W0p + n * 17;
        float bias = 0.f;
        #pragma unroll
        for (int t = 0; t < 8; t++) bias = fmaf(fv[t], w0r[9 + t], bias);

        float v0 = w0r[2 * q], v1 = w0r[2 * q + 1];
        b0h[j][0] = pack_rn(rn_bf(v0), rn_bf(v1));
        b0m[j][0] = pack_rn(v0 - rn_bf(v0), v1 - rn_bf(v1));
        if (q == 0) {
            float u0 = w0r[8], u1 = bias;
            b0h[j][1] = pack_rn(rn_bf(u0), rn_bf(u1));
            b0m[j][1] = pack_rn(u0 - rn_bf(u0), u1 - rn_bf(u1));
        } else {
            b0h[j][1] = 0u; b0m[j][1] = 0u;
        }
        w3r[j][0] = W3[p * 32 + 8 * j + 2 * q];
        w3r[j][1] = W3[p * 32 + 8 * j + 2 * q + 1];
    }

    // ---- warp 0 builds the L1/L2 tables ----
    if (w == 0) {
        #pragma unroll
        for (int j = 0; j < 4; j++) {
            const int n = g + 8 * j;
            const float* w1r = W1 + p * 1024 + n * 32;
            const float* w2r = W2 + p * 1024 + n * 32;
            #pragma unroll
            for (int kb = 0; kb < 2; kb++) {
                int k0 = 2 * q + 16 * kb;
                float a0 = w1r[k0], a1 = w1r[k0 + 1];
                float a2 = w1r[k0 + 8], a3 = w1r[k0 + 9];
                sB1[lane][kb * 8 + 0 + j]      = pack_rn(rn_bf(a0), rn_bf(a1));
                sB1[lane][kb * 8 + 4 + j]      = pack_rn(rn_bf(a2), rn_bf(a3));
                sB1[lane][16 + kb * 8 + 0 + j] = pack_rn(a0 - rn_bf(a0), a1 - rn_bf(a1));
                sB1[lane][16 + kb * 8 + 4 + j] = pack_rn(a2 - rn_bf(a2), a3 - rn_bf(a3));
                float c0 = w2r[k0], c1 = w2r[k0 + 1];
                float c2 = w2r[k0 + 8], c3 = w2r[k0 + 9];
                sB2[lane][kb * 8 + 0 + j]      = pack_rn(rn_bf(c0), rn_bf(c1));
                sB2[lane][kb * 8 + 4 + j]      = pack_rn(rn_bf(c2), rn_bf(c3));
                sB2[lane][16 + kb * 8 + 0 + j] = pack_rn(c0 - rn_bf(c0), c1 - rn_bf(c1));
                sB2[lane][16 + kb * 8 + 4 + j] = pack_rn(c2 - rn_bf(c2), c3 - rn_bf(c3));
            }
        }
    }
    __syncthreads();

    const uint4* tb1 = (const uint4*)&sB1[lane][0];
    const uint4* tb2 = (const uint4*)&sB2[lane][0];

    const long long pbase = (long long)(b * P_ + p) * N_ + (long long)chunk * CHUNK;
    const long long obase = (long long)b * N_ + (long long)chunk * CHUNK;

    for (int it = 0; it < ITERS; it++) {
        const int mwarp = it * 128 + w * 32;

        __syncwarp();
        {
            const float* pt = points + (pbase + mwarp + lane) * 3;
            float x = __ldg(pt), y = __ldg(pt + 1), z = __ldg(pt + 2);
            float v[10];
            v[0] = x; v[1] = y; v[2] = z;
            __sincosf(x, &v[3], &v[6]);
            __sincosf(y, &v[4], &v[7]);
            __sincosf(z, &v[5], &v[8]);
            v[9] = 1.f;
            #pragma unroll
            for (int t = 0; t < 5; t++) {
                float a = v[2 * t], c = v[2 * t + 1];
                sPEh[w][lane][t] = pack_rn(rn_bf(a), rn_bf(c));
                sPEm[w][lane][t] = pack_rn(a - rn_bf(a), c - rn_bf(c));
            }
            #pragma unroll
            for (int t = 5; t < 8; t++) {
                sPEh[w][lane][t] = 0u;
                sPEm[w][lane][t] = 0u;
            }
        }
        __syncwarp();

        #pragma unroll
        for (int mt = 0; mt < 2; mt++) {
            const int rbase = mt * 16;

            uint32_t A0h[4], A0m[4];
            A0h[0] = sPEh[w][rbase + g][q];
            A0h[1] = sPEh[w][rbase + g + 8][q];
            A0h[2] = sPEh[w][rbase + g][q + 4];
            A0h[3] = sPEh[w][rbase + g + 8][q + 4];
            A0m[0] = sPEm[w][rbase + g][q];
            A0m[1] = sPEm[w][rbase + g + 8][q];
            A0m[2] = sPEm[w][rbase + g][q + 4];
            A0m[3] = sPEm[w][rbase + g + 8][q + 4];

            float C[4][4];
            #pragma unroll
            for (int n = 0; n < 4; n++)
                C[n][0] = C[n][1] = C[n][2] = C[n][3] = 0.f;

            // ---- L0 (K=16), term-major ----
            #pragma unroll
            for (int n = 0; n < 4; n++)
                mma16816(C[n], A0h[0], A0h[1], A0h[2], A0h[3], b0h[n][0], b0h[n][1]);
            #pragma unroll
            for (int n = 0; n < 4; n++)
                mma16816(C[n], A0m[0], A0m[1], A0m[2], A0m[3], b0h[n][0], b0h[n][1]);
            #pragma unroll
            for (int n = 0; n < 4; n++)
                mma16816(C[n], A0h[0], A0h[1], A0h[2], A0h[3], b0m[n][0], b0m[n][1]);

            uint32_t Ah[2][4], Am[2][4];
            #pragma unroll
            for (int n = 0; n < 4; n++) {
                float c0 = fmaxf(C[n][0], 0.f), c1 = fmaxf(C[n][1], 0.f);
                float c2 = fmaxf(C[n][2], 0.f), c3 = fmaxf(C[n][3], 0.f);
                int kb = n >> 1, pos = (n & 1) * 2;
                Ah[kb][pos]     = pack_hi16(c0, c1);
                Ah[kb][pos + 1] = pack_hi16(c2, c3);
                Am[kb][pos]     = pack_hi16(c0 - trunc_bf(c0), c1 - trunc_bf(c1));
                Am[kb][pos + 1] = pack_hi16(c2 - trunc_bf(c2), c3 - trunc_bf(c3));
            }

            // ---- L1 (K=32), term-major; B quads from smem ----
            #pragma unroll
            for (int n = 0; n < 4; n++)
                C[n][0] = C[n][1] = C[n][2] = C[n][3] = 0.f;
            {
                uint4 h0 = tb1[0], h1 = tb1[1], h2 = tb1[2], h3 = tb1[3];
                MMA_T4(C, Ah[0], h0, h1);
                MMA_T4(C, Ah[1], h2, h3);
                MMA_T4(C, Am[0], h0, h1);
                MMA_T4(C, Am[1], h2, h3);
                uint4 m0 = tb1[4], m1 = tb1[5], m2 = tb1[6], m3 = tb1[7];
                MMA_T4(C, Ah[0], m0, m1);
                MMA_T4(C, Ah[1], m2, m3);
            }
            #pragma unroll
            for (int n = 0; n < 4; n++) {
                float c0 = fmaxf(C[n][0], 0.f), c1 = fmaxf(C[n][1], 0.f);
                float c2 = fmaxf(C[n][2], 0.f), c3 = fmaxf(C[n][3], 0.f);
                int kb = n >> 1, pos = (n & 1) * 2;
                Ah[kb][pos]     = pack_hi16(c0, c1);
                Ah[kb][pos + 1] = pack_hi16(c2, c3);
                Am[kb][pos]     = pack_hi16(c0 - trunc_bf(c0), c1 - trunc_bf(c1));
                Am[kb][pos + 1] = pack_hi16(c2 - trunc_bf(c2), c3 - trunc_bf(c3));
            }

            // ---- L2 (K=32) ----
            #pragma unroll
            for (int n = 0; n < 4; n++)
                C[n][0] = C[n][1] = C[n][2] = C[n][3] = 0.f;
            {
                uint4 h0 = tb2[0], h1 = tb2[1], h2 = tb2[2], h3 = tb2[3];
                MMA_T4(C, Ah[0], h0, h1);
                MMA_T4(C, Ah[1], h2, h3);
                MMA_T4(C, Am[0], h0, h1);
                MMA_T4(C, Am[1], h2, h3);
                uint4 m0 = tb2[4], m1 = tb2[5], m2 = tb2[6], m3 = tb2[7];
                MMA_T4(C, Ah[0], m0, m1);
                MMA_T4(C, Ah[1], m2, m3);
            }

            // ---- L3: relu + dot(w3) + butterfly over q-group ----
            float s0 = 0.f, s1 = 0.f;
            #pragma unroll
            for (int n = 0; n < 4; n++) {
                s0 = fmaf(fmaxf(C[n][0], 0.f), w3r[n][0], s0);
                s0 = fmaf(fmaxf(C[n][1], 0.f), w3r[n][1], s0);
                s1 = fmaf(fmaxf(C[n][2], 0.f), w3r[n][0], s1);
                s1 = fmaf(fmaxf(C[n][3], 0.f), w3r[n][1], s1);
            }
            s0 += __shfl_xor_sync(0xFFFFFFFFu, s0, 1);
            s0 += __shfl_xor_sync(0xFFFFFFFFu, s0, 2);
            s1 += __shfl_xor_sync(0xFFFFFFFFu, s1, 1);
            s1 += __shfl_xor_sync(0xFFFFFFFFu, s1, 2);
            if (q == 0) {
                long long m0 = obase + mwarp + rbase + g;
                out[m0 * P_ + p]       = s0;
                out[(m0 + 8) * P_ + p] = s1;
            }
        }
    }
}

extern "C" void kernel_launch(void* const* d_in, const int* in_sizes, int n_in,
                              void* d_out, int out_size)
{
    const float* points   = (const float*)d_in[0];
    const float* features = (const float*)d_in[1];
    const float* W0       = (const float*)d_in[2];
    const float* W1       = (const float*)d_in[3];
    const float* W2       = (const float*)d_in[4];
    const float* W3       = (const float*)d_in[5];
    float* out = (float*)d_out;

    dim3 grid(N_ / CHUNK, P_, B_);
    sdfvae_mma_kernel<<<grid, THREADS>>>(points, features, W0, W1, W2, W3, out);
}

// round 11
// speedup vs baseline: 1.0736x; 1.0736x over previous
#include <cuda_runtime.h>
#include <cuda_bf16.h>
#include <cstdint>

// SDFVae per-part MLP on mma.sync.m16n8k16 (bf16 hi+mid split, f32 accum).
// R11 = R9 (register-resident B-frags) + term-major MMA issue: the 3 split
// terms each issue 4 independent n-chains, so same-accumulator MMAs are >=4
// issue slots apart (covers HMMA accumulate latency).
//   d_in[0] points [8,42,16384,3] f32   d_in[1] features [8,336] f32
//   d_in[2] W0 [42,32,17]  d_in[3] W1 [42,32,32]
//   d_in[4] W2 [42,32,32]  d_in[5] W3 [42,1,32]
//   out [8,16384,42] f32

#define B_ 8
#define P_ 42
#define N_ 16384
#define THREADS 128
#define CHUNK 2048
#define ITERS (CHUNK / 128)   // 16

__device__ __forceinline__ void mma16816(float c[4],
    uint32_t a0, uint32_t a1, uint32_t a2, uint32_t a3,
    uint32_t b0, uint32_t b1)
{
    asm volatile(
        "mma.sync.aligned.m16n8k16.row.col.f32.bf16.bf16.f32 "
        "{%0,%1,%2,%3}, {%4,%5,%6,%7}, {%8,%9}, {%0,%1,%2,%3};"
        : "+f"(c[0]), "+f"(c[1]), "+f"(c[2]), "+f"(c[3])
        : "r"(a0), "r"(a1), "r"(a2), "r"(a3), "r"(b0), "r"(b1));
}
__device__ __forceinline__ uint32_t pack_rn(float lo, float hi) {
    uint32_t r;
    asm("cvt.rn.satfinite.bf16x2.f32 %0, %1, %2;" : "=r"(r) : "f"(hi), "f"(lo));
    return r;
}
__device__ __forceinline__ uint32_t pack_hi16(float lo, float hi) {
    return __byte_perm(__float_as_uint(lo), __float_as_uint(hi), 0x7632);
}
__device__ __forceinline__ float trunc_bf(float v) {
    return __uint_as_float(__float_as_uint(v) & 0xFFFF0000u);
}
__device__ __forceinline__ float rn_bf(float v) {
    return __bfloat162float(__float2bfloat16(v));
}

__global__ __launch_bounds__(THREADS)
void sdfvae_mma_kernel(const float* __restrict__ points,
                       const float* __restrict__ features,
                       const float* __restrict__ W0,
                       const float* __restrict__ W1,
                       const float* __restrict__ W2,
                       const float* __restrict__ W3,
                       float* __restrict__ out)
{
    const int chunk = blockIdx.x, p = blockIdx.y, b = blockIdx.z;
    const int tid = threadIdx.x;
    const int w = tid >> 5, lane = tid & 31;
    const int g = lane >> 2, q = lane & 3;   // groupID, thread-in-group

    __shared__ uint32_t sPEh[4][32][9];
    __shared__ uint32_t sPEm[4][32][9];

    // B fragments in registers (built once from gmem)
    uint32_t b0h[4][2], b0m[4][2];         // L0  [ntile][b0,b1]
    uint32_t b1h[4][2][2], b1m[4][2][2];   // L1  [ntile][kb][b0,b1]
    uint32_t b2h[4][2][2], b2m[4][2][2];   // L2
    float    w3r[4][2];

    const float* W0p = W0 + p * 32 * 17;
    const float* fv  = features + (b * P_ + p) * 8;

    #pragma unroll
    for (int j = 0; j < 4; j++) {
        const int n = g + 8 * j;
        const float* w0r = W0p + n * 17;
        float bias = 0.f;
        #pragma unroll
        for (int t = 0; t < 8; t++) bias = fmaf(fv[t], w0r[9 + t], bias);

        float v0 = w0r[2 * q], v1 = w0r[2 * q + 1];
        b0h[j][0] = pack_rn(rn_bf(v0), rn_bf(v1));
        b0m[j][0] = pack_rn(v0 - rn_bf(v0), v1 - rn_bf(v1));
        if (q == 0) {
            float u0 = w0r[8], u1 = bias;
            b0h[j][1] = pack_rn(rn_bf(u0), rn_bf(u1));
            b0m[j][1] = pack_rn(u0 - rn_bf(u0), u1 - rn_bf(u1));
        } else {
            b0h[j][1] = 0u; b0m[j][1] = 0u;
        }

        const float* w1r = W1 + p * 1024 + n * 32;
        const float* w2r = W2 + p * 1024 + n * 32;
        #pragma unroll
        for (int kb = 0; kb < 2; kb++) {
            int k0 = 2 * q + 16 * kb;
            float a0 = w1r[k0], a1 = w1r[k0 + 1], a2 = w1r[k0 + 8], a3 = w1r[k0 + 9];
            b1h[j][kb][0] = pack_rn(rn_bf(a0), rn_bf(a1));
            b1m[j][kb][0] = pack_rn(a0 - rn_bf(a0), a1 - rn_bf(a1));
            b1h[j][kb][1] = pack_rn(rn_bf(a2), rn_bf(a3));
            b1m[j][kb][1] = pack_rn(a2 - rn_bf(a2), a3 - rn_bf(a3));
            float c0 = w2r[k0], c1 = w2r[k0 + 1], c2 = w2r[k0 + 8], c3 = w2r[k0 + 9];
            b2h[j][kb][0] = pack_rn(rn_bf(c0), rn_bf(c1));
            b2m[j][kb][0] = pack_rn(c0 - rn_bf(c0), c1 - rn_bf(c1));
            b2h[j][kb][1] = pack_rn(rn_bf(c2), rn_bf(c3));
            b2m[j][kb][1] = pack_rn(c2 - rn_bf(c2), c3 - rn_bf(c3));
        }
        w3r[j][0] = W3[p * 32 + 8 * j + 2 * q];
        w3r[j][1] = W3[p * 32 + 8 * j + 2 * q + 1];
    }

    const long long pbase = (long long)(b * P_ + p) * N_ + (long long)chunk * CHUNK;
    const long long obase = (long long)b * N_ + (long long)chunk * CHUNK;

    for (int it = 0; it < ITERS; it++) {
        const int mwarp = it * 128 + w * 32;

        __syncwarp();
        {
            const float* pt = points + (pbase + mwarp + lane) * 3;
            float x = __ldg(pt), y = __ldg(pt + 1), z = __ldg(pt + 2);
            float v[10];
            v[0] = x; v[1] = y; v[2] = z;
            __sincosf(x, &v[3], &v[6]);
            __sincosf(y, &v[4], &v[7]);
            __sincosf(z, &v[5], &v[8]);
            v[9] = 1.f;
            #pragma unroll
            for (int t = 0; t < 5; t++) {
                float a = v[2 * t], c = v[2 * t + 1];
                sPEh[w][lane][t] = pack_rn(rn_bf(a), rn_bf(c));
                sPEm[w][lane][t] = pack_rn(a - rn_bf(a), c - rn_bf(c));
            }
            #pragma unroll
            for (int t = 5; t < 8; t++) {
                sPEh[w][lane][t] = 0u;
                sPEm[w][lane][t] = 0u;
            }
        }
        __syncwarp();

        #pragma unroll
        for (int mt = 0; mt < 2; mt++) {
            const int rbase = mt * 16;

            uint32_t A0h[4], A0m[4];
            A0h[0] = sPEh[w][rbase + g][q];
            A0h[1] = sPEh[w][rbase + g + 8][q];
            A0h[2] = sPEh[w][rbase + g][q + 4];
            A0h[3] = sPEh[w][rbase + g + 8][q + 4];
            A0m[0] = sPEm[w][rbase + g][q];
            A0m[1] = sPEm[w][rbase + g + 8][q];
            A0m[2] = sPEm[w][rbase + g][q + 4];
            A0m[3] = sPEm[w][rbase + g + 8][q + 4];

            float C[4][4];
            #pragma unroll
            for (int n = 0; n < 4; n++)
                C[n][0] = C[n][1] = C[n][2] = C[n][3] = 0.f;

            // ---- L0 (K=16), term-major ----
            #pragma unroll
            for (int n = 0; n < 4; n++)
                mma16816(C[n], A0h[0], A0h[1], A0h[2], A0h[3], b0h[n][0], b0h[n][1]);
            #pragma unroll
            for (int n = 0; n < 4; n++)
                mma16816(C[n], A0m[0], A0m[1], A0m[2], A0m[3], b0h[n][0], b0h[n][1]);
            #pragma unroll
            for (int n = 0; n < 4; n++)
                mma16816(C[n], A0h[0], A0h[1], A0h[2], A0h[3], b0m[n][0], b0m[n][1]);

            uint32_t Ah[2][4], Am[2][4];
            #pragma unroll
            for (int n = 0; n < 4; n++) {
                float c0 = fmaxf(C[n][0], 0.f), c1 = fmaxf(C[n][1], 0.f);
                float c2 = fmaxf(C[n][2], 0.f), c3 = fmaxf(C[n][3], 0.f);
                int kb = n >> 1, pos = (n & 1) * 2;
                Ah[kb][pos]     = pack_hi16(c0, c1);
                Ah[kb][pos + 1] = pack_hi16(c2, c3);
                Am[kb][pos]     = pack_hi16(c0 - trunc_bf(c0), c1 - trunc_bf(c1));
                Am[kb][pos + 1] = pack_hi16(c2 - trunc_bf(c2), c3 - trunc_bf(c3));
            }

            // ---- L1 (K=32), term-major ----
            #pragma unroll
            for (int n = 0; n < 4; n++)
                C[n][0] = C[n][1] = C[n][2] = C[n][3] = 0.f;
            #pragma unroll
            for (int kb = 0; kb < 2; kb++)
                #pragma unroll
                for (int n = 0; n < 4; n++)
                    mma16816(C[n], Ah[kb][0], Ah[kb][1], Ah[kb][2], Ah[kb][3],
                             b1h[n][kb][0], b1h[n][kb][1]);
            #pragma unroll
            for (int kb = 0; kb < 2; kb++)
                #pragma unroll
                for (int n = 0; n < 4; n++)
                    mma16816(C[n], Am[kb][0], Am[kb][1], Am[kb][2], Am[kb][3],
                             b1h[n][kb][0], b1h[n][kb][1]);
            #pragma unroll
            for (int kb = 0; kb < 2; kb++)
                #pragma unroll
                for (int n = 0; n < 4; n++)
                    mma16816(C[n], Ah[kb][0], Ah[kb][1], Ah[kb][2], Ah[kb][3],
                             b1m[n][kb][0], b1m[n][kb][1]);
            #pragma unroll
            for (int n = 0; n < 4; n++) {
                float c0 = fmaxf(C[n][0], 0.f), c1 = fmaxf(C[n][1], 0.f);
                float c2 = fmaxf(C[n][2], 0.f), c3 = fmaxf(C[n][3], 0.f);
                int kb = n >> 1, pos = (n & 1) * 2;
                Ah[kb][pos]     = pack_hi16(c0, c1);
                Ah[kb][pos + 1] = pack_hi16(c2, c3);
                Am[kb][pos]     = pack_hi16(c0 - trunc_bf(c0), c1 - trunc_bf(c1));
                Am[kb][pos + 1] = pack_hi16(c2 - trunc_bf(c2), c3 - trunc_bf(c3));
            }

            // ---- L2 (K=32), term-major ----
            #pragma unroll
            for (int n = 0; n < 4; n++)
                C[n][0] = C[n][1] = C[n][2] = C[n][3] = 0.f;
            #pragma unroll
            for (int kb = 0; kb < 2; kb++)
                #pragma unroll
                for (int n = 0; n < 4; n++)
                    mma16816(C[n], Ah[kb][0], Ah[kb][1], Ah[kb][2], Ah[kb][3],
                             b2h[n][kb][0], b2h[n][kb][1]);
            #pragma unroll
            for (int kb = 0; kb < 2; kb++)
                #pragma unroll
                for (int n = 0; n < 4; n++)
                    mma16816(C[n], Am[kb][0], Am[kb][1], Am[kb][2], Am[kb][3],
                             b2h[n][kb][0], b2h[n][kb][1]);
            #pragma unroll
            for (int kb = 0; kb < 2; kb++)
                #pragma unroll
                for (int n = 0; n < 4; n++)
                    mma16816(C[n], Ah[kb][0], Ah[kb][1], Ah[kb][2], Ah[kb][3],
                             b2m[n][kb][0], b2m[n][kb][1]);

            // ---- L3: relu + per-thread dot + butterfly over q-group ----
            float s0 = 0.f, s1 = 0.f;
            #pragma unroll
            for (int n = 0; n < 4; n++) {
                s0 = fmaf(fmaxf(C[n][0], 0.f), w3r[n][0], s0);
                s0 = fmaf(fmaxf(C[n][1], 0.f), w3r[n][1], s0);
                s1 = fmaf(fmaxf(C[n][2], 0.f), w3r[n][0], s1);
                s1 = fmaf(fmaxf(C[n][3], 0.f), w3r[n][1], s1);
            }
            s0 += __shfl_xor_sync(0xFFFFFFFFu, s0, 1);
            s0 += __shfl_xor_sync(0xFFFFFFFFu, s0, 2);
            s1 += __shfl_xor_sync(0xFFFFFFFFu, s1, 1);
            s1 += __shfl_xor_sync(0xFFFFFFFFu, s1, 2);
            if (q == 0) {
                long long m0 = obase + mwarp + rbase + g;
                out[m0 * P_ + p]       = s0;
                out[(m0 + 8) * P_ + p] = s1;
            }
        }
    }
}

extern "C" void kernel_launch(void* const* d_in, const int* in_sizes, int n_in,
                              void* d_out, int out_size)
{
    const float* points   = (const float*)d_in[0];
    const float* features = (const float*)d_in[1];
    const float* W0       = (const float*)d_in[2];
    const float* W1       = (const float*)d_in[3];
    const float* W2       = (const float*)d_in[4];
    const float* W3       = (const float*)d_in[5];
    float* out = (float*)d_out;

    dim3 grid(N_ / CHUNK, P_, B_);
    sdfvae_mma_kernel<<<grid, THREADS>>>(points, features, W0, W1, W2, W3, out);
}

// round 12
// speedup vs baseline: 1.0801x; 1.0060x over previous
#include <cuda_runtime.h>
#include <cuda_bf16.h>
#include <cstdint>

// SDFVae per-part MLP on mma.sync.m16n8k16 (bf16 hi+mid split, f32 accum).
// R12: both 16-row m-tiles processed as one fused stream (8 independent
// accumulator chains; tile A's transition ALU overlaps tile B's MMAs).
//   d_in[0] points [8,42,16384,3] f32   d_in[1] features [8,336] f32
//   d_in[2] W0 [42,32,17]  d_in[3] W1 [42,32,32]
//   d_in[4] W2 [42,32,32]  d_in[5] W3 [42,1,32]
//   out [8,16384,42] f32

#define B_ 8
#define P_ 42
#define N_ 16384
#define THREADS 128
#define CHUNK 2048
#define ITERS (CHUNK / 128)   // 16

__device__ __forceinline__ void mma16816(float c[4],
    const uint32_t a[4], uint32_t b0, uint32_t b1)
{
    asm volatile(
        "mma.sync.aligned.m16n8k16.row.col.f32.bf16.bf16.f32 "
        "{%0,%1,%2,%3}, {%4,%5,%6,%7}, {%8,%9}, {%0,%1,%2,%3};"
        : "+f"(c[0]), "+f"(c[1]), "+f"(c[2]), "+f"(c[3])
        : "r"(a[0]), "r"(a[1]), "r"(a[2]), "r"(a[3]), "r"(b0), "r"(b1));
}
__device__ __forceinline__ uint32_t pack_rn(float lo, float hi) {
    uint32_t r;
    asm("cvt.rn.satfinite.bf16x2.f32 %0, %1, %2;" : "=r"(r) : "f"(hi), "f"(lo));
    return r;
}
__device__ __forceinline__ uint32_t pack_hi16(float lo, float hi) {
    return __byte_perm(__float_as_uint(lo), __float_as_uint(hi), 0x7632);
}
__device__ __forceinline__ float trunc_bf(float v) {
    return __uint_as_float(__float_as_uint(v) & 0xFFFF0000u);
}
__device__ __forceinline__ float rn_bf(float v) {
    return __bfloat162float(__float2bfloat16(v));
}

__global__ __launch_bounds__(THREADS)
void sdfvae_mma_kernel(const float* __restrict__ points,
                       const float* __restrict__ features,
                       const float* __restrict__ W0,
                       const float* __restrict__ W1,
                       const float* __restrict__ W2,
                       const float* __restrict__ W3,
                       float* __restrict__ out)
{
    const int chunk = blockIdx.x, p = blockIdx.y, b = blockIdx.z;
    const int tid = threadIdx.x;
    const int w = tid >> 5, lane = tid & 31;
    const int g = lane >> 2, q = lane & 3;

    __shared__ uint32_t sPEh[4][32][9];
    __shared__ uint32_t sPEm[4][32][9];

    // B fragments in registers (built once from gmem)
    uint32_t b0h[4][2], b0m[4][2];
    uint32_t b1h[4][2][2], b1m[4][2][2];
    uint32_t b2h[4][2][2], b2m[4][2][2];
    float    w3r[4][2];

    const float* W0p = W0 + p * 32 * 17;
    const float* fv  = features + (b * P_ + p) * 8;

    #pragma unroll
    for (int j = 0; j < 4; j++) {
        const int n = g + 8 * j;
        const float* w0r = W0p + n * 17;
        float bias = 0.f;
        #pragma unroll
        for (int t = 0; t < 8; t++) bias = fmaf(fv[t], w0r[9 + t], bias);

        float v0 = w0r[2 * q], v1 = w0r[2 * q + 1];
        b0h[j][0] = pack_rn(rn_bf(v0), rn_bf(v1));
        b0m[j][0] = pack_rn(v0 - rn_bf(v0), v1 - rn_bf(v1));
        if (q == 0) {
            float u0 = w0r[8], u1 = bias;
            b0h[j][1] = pack_rn(rn_bf(u0), rn_bf(u1));
            b0m[j][1] = pack_rn(u0 - rn_bf(u0), u1 - rn_bf(u1));
        } else {
            b0h[j][1] = 0u; b0m[j][1] = 0u;
        }

        const float* w1r = W1 + p * 1024 + n * 32;
        const float* w2r = W2 + p * 1024 + n * 32;
        #pragma unroll
        for (int kb = 0; kb < 2; kb++) {
            int k0 = 2 * q + 16 * kb;
            float a0 = w1r[k0], a1 = w1r[k0 + 1], a2 = w1r[k0 + 8], a3 = w1r[k0 + 9];
            b1h[j][kb][0] = pack_rn(rn_bf(a0), rn_bf(a1));
            b1m[j][kb][0] = pack_rn(a0 - rn_bf(a0), a1 - rn_bf(a1));
            b1h[j][kb][1] = pack_rn(rn_bf(a2), rn_bf(a3));
            b1m[j][kb][1] = pack_rn(a2 - rn_bf(a2), a3 - rn_bf(a3));
            float c0 = w2r[k0], c1 = w2r[k0 + 1], c2 = w2r[k0 + 8], c3 = w2r[k0 + 9];
            b2h[j][kb][0] = pack_rn(rn_bf(c0), rn_bf(c1));
            b2m[j][kb][0] = pack_rn(c0 - rn_bf(c0), c1 - rn_bf(c1));
            b2h[j][kb][1] = pack_rn(rn_bf(c2), rn_bf(c3));
            b2m[j][kb][1] = pack_rn(c2 - rn_bf(c2), c3 - rn_bf(c3));
        }
        w3r[j][0] = W3[p * 32 + 8 * j + 2 * q];
        w3r[j][1] = W3[p * 32 + 8 * j + 2 * q + 1];
    }

    const long long pbase = (long long)(b * P_ + p) * N_ + (long long)chunk * CHUNK;
    const long long obase = (long long)b * N_ + (long long)chunk * CHUNK;

    for (int it = 0; it < ITERS; it++) {
        const int mwarp = it * 128 + w * 32;

        __syncwarp();
        {
            const float* pt = points + (pbase + mwarp + lane) * 3;
            float x = __ldg(pt), y = __ldg(pt + 1), z = __ldg(pt + 2);
            float v[10];
            v[0] = x; v[1] = y; v[2] = z;
            __sincosf(x, &v[3], &v[6]);
            __sincosf(y, &v[4], &v[7]);
            __sincosf(z, &v[5], &v[8]);
            v[9] = 1.f;
            #pragma unroll
            for (int t = 0; t < 5; t++) {
                float a = v[2 * t], c = v[2 * t + 1];
                sPEh[w][lane][t] = pack_rn(rn_bf(a), rn_bf(c));
                sPEm[w][lane][t] = pack_rn(a - rn_bf(a), c - rn_bf(c));
            }
            #pragma unroll
            for (int t = 5; t < 8; t++) {
                sPEh[w][lane][t] = 0u;
                sPEm[w][lane][t] = 0u;
            }
        }
        __syncwarp();

        // ---- fused processing of both 16-row tiles ----
        uint32_t A0h[2][4], A0m[2][4];
        #pragma unroll
        for (int t = 0; t < 2; t++) {
            const int rb = t * 16;
            A0h[t][0] = sPEh[w][rb + g][q];
            A0h[t][1] = sPEh[w][rb + g + 8][q];
            A0h[t][2] = sPEh[w][rb + g][q + 4];
            A0h[t][3] = sPEh[w][rb + g + 8][q + 4];
            A0m[t][0] = sPEm[w][rb + g][q];
            A0m[t][1] = sPEm[w][rb + g + 8][q];
            A0m[t][2] = sPEm[w][rb + g][q + 4];
            A0m[t][3] = sPEm[w][rb + g + 8][q + 4];
        }

        float C[2][4][4];
        #pragma unroll
        for (int t = 0; t < 2; t++)
            #pragma unroll
            for (int n = 0; n < 4; n++)
                C[t][n][0] = C[t][n][1] = C[t][n][2] = C[t][n][3] = 0.f;

        // ---- L0 (K=16): 3 terms x 2 tiles x 4 n = 24 MMAs, 8 indep chains ----
        #pragma unroll
        for (int t = 0; t < 2; t++)
            #pragma unroll
            for (int n = 0; n < 4; n++) {
                mma16816(C[t][n], A0h[t], b0h[n][0], b0h[n][1]);
                mma16816(C[t][n], A0m[t], b0h[n][0], b0h[n][1]);
                mma16816(C[t][n], A0h[t], b0m[n][0], b0m[n][1]);
            }

        uint32_t Ah[2][2][4], Am[2][2][4];
        #pragma unroll
        for (int t = 0; t < 2; t++)
            #pragma unroll
            for (int n = 0; n < 4; n++) {
                float c0 = fmaxf(C[t][n][0], 0.f), c1 = fmaxf(C[t][n][1], 0.f);
                float c2 = fmaxf(C[t][n][2], 0.f), c3 = fmaxf(C[t][n][3], 0.f);
                int kb = n >> 1, pos = (n & 1) * 2;
                Ah[t][kb][pos]     = pack_hi16(c0, c1);
                Ah[t][kb][pos + 1] = pack_hi16(c2, c3);
                Am[t][kb][pos]     = pack_hi16(c0 - trunc_bf(c0), c1 - trunc_bf(c1));
                Am[t][kb][pos + 1] = pack_hi16(c2 - trunc_bf(c2), c3 - trunc_bf(c3));
            }

        // ---- L1 (K=32): 48 MMAs ----
        #pragma unroll
        for (int t = 0; t < 2; t++)
            #pragma unroll
            for (int n = 0; n < 4; n++)
                C[t][n][0] = C[t][n][1] = C[t][n][2] = C[t][n][3] = 0.f;
        #pragma unroll
        for (int t = 0; t < 2; t++)
            #pragma unroll
            for (int n = 0; n < 4; n++)
                #pragma unroll
                for (int kb = 0; kb < 2; kb++) {
                    mma16816(C[t][n], Ah[t][kb], b1h[n][kb][0], b1h[n][kb][1]);
                    mma16816(C[t][n], Am[t][kb], b1h[n][kb][0], b1h[n][kb][1]);
                    mma16816(C[t][n], Ah[t][kb], b1m[n][kb][0], b1m[n][kb][1]);
                }
        #pragma unroll
        for (int t = 0; t < 2; t++)
            #pragma unroll
            for (int n = 0; n < 4; n++) {
                float c0 = fmaxf(C[t][n][0], 0.f), c1 = fmaxf(C[t][n][1], 0.f);
                float c2 = fmaxf(C[t][n][2], 0.f), c3 = fmaxf(C[t][n][3], 0.f);
                int kb = n >> 1, pos = (n & 1) * 2;
                Ah[t][kb][pos]     = pack_hi16(c0, c1);
                Ah[t][kb][pos + 1] = pack_hi16(c2, c3);
                Am[t][kb][pos]     = pack_hi16(c0 - trunc_bf(c0), c1 - trunc_bf(c1));
                Am[t][kb][pos + 1] = pack_hi16(c2 - trunc_bf(c2), c3 - trunc_bf(c3));
            }

        // ---- L2 (K=32): 48 MMAs ----
        #pragma unroll
        for (int t = 0; t < 2; t++)
            #pragma unroll
            for (int n = 0; n < 4; n++)
                C[t][n][0] = C[t][n][1] = C[t][n][2] = C[t][n][3] = 0.f;
        #pragma unroll
        for (int t = 0; t < 2; t++)
            #pragma unroll
            for (int n = 0; n < 4; n++)
                #pragma unroll
                for (int kb = 0; kb < 2; kb++) {
                    mma16816(C[t][n], Ah[t][kb], b2h[n][kb][0], b2h[n][kb][1]);
                    mma16816(C[t][n], Am[t][kb], b2h[n][kb][0], b2h[n][kb][1]);
                    mma16816(C[t][n], Ah[t][kb], b2m[n][kb][0], b2m[n][kb][1]);
                }

        // ---- L3: relu + per-thread dot + butterfly over q-group ----
        #pragma unroll
        for (int t = 0; t < 2; t++) {
            float s0 = 0.f, s1 = 0.f;
            #pragma unroll
            for (int n = 0; n < 4; n++) {
                s0 = fmaf(fmaxf(C[t][n][0], 0.f), w3r[n][0], s0);
                s0 = fmaf(fmaxf(C[t][n][1], 0.f), w3r[n][1], s0);
                s1 = fmaf(fmaxf(C[t][n][2], 0.f), w3r[n][0], s1);
                s1 = fmaf(fmaxf(C[t][n][3], 0.f), w3r[n][1], s1);
            }
            s0 += __shfl_xor_sync(0xFFFFFFFFu, s0, 1);
            s0 += __shfl_xor_sync(0xFFFFFFFFu, s0, 2);
            s1 += __shfl_xor_sync(0xFFFFFFFFu, s1, 1);
            s1 += __shfl_xor_sync(0xFFFFFFFFu, s1, 2);
            if (q == 0) {
                long long m0 = obase + mwarp + t * 16 + g;
                out[m0 * P_ + p]       = s0;
                out[(m0 + 8) * P_ + p] = s1;
            }
        }
    }
}

extern "C" void kernel_launch(void* const* d_in, const int* in_sizes, int n_in,
                              void* d_out, int out_size)
{
    const float* points   = (const float*)d_in[0];
    const float* features = (const float*)d_in[1];
    const float* W0       = (const float*)d_in[2];
    const float* W1       = (const float*)d_in[3];
    const float* W2       = (const float*)d_in[4];
    const float* W3       = (const float*)d_in[5];
    float* out = (float*)d_out;

    dim3 grid(N_ / CHUNK, P_, B_);
    sdfvae_mma_kernel<<<grid, THREADS>>>(points, features, W0, W1, W2, W3, out);
}

// round 13
// speedup vs baseline: 1.1052x; 1.0233x over previous
#include <cuda_runtime.h>
#include <cuda_bf16.h>
#include <cstdint>

// SDFVae per-part MLP on mma.sync.m16n8k16 (bf16 hi+mid split, f32 accum).
// R13 = R12 + points prefetch: next iteration's 3-float point is loaded into
// registers before the current MMA chain, hiding LDG latency (the serial
// per-iteration prologue LDG->sincos->stage->frags was on the critical path).
//   d_in[0] points [8,42,16384,3] f32   d_in[1] features [8,336] f32
//   d_in[2] W0 [42,32,17]  d_in[3] W1 [42,32,32]
//   d_in[4] W2 [42,32,32]  d_in[5] W3 [42,1,32]
//   out [8,16384,42] f32

#define B_ 8
#define P_ 42
#define N_ 16384
#define THREADS 128
#define CHUNK 2048
#define ITERS (CHUNK / 128)   // 16

__device__ __forceinline__ void mma16816(float c[4],
    const uint32_t a[4], uint32_t b0, uint32_t b1)
{
    asm volatile(
        "mma.sync.aligned.m16n8k16.row.col.f32.bf16.bf16.f32 "
        "{%0,%1,%2,%3}, {%4,%5,%6,%7}, {%8,%9}, {%0,%1,%2,%3};"
        : "+f"(c[0]), "+f"(c[1]), "+f"(c[2]), "+f"(c[3])
        : "r"(a[0]), "r"(a[1]), "r"(a[2]), "r"(a[3]), "r"(b0), "r"(b1));
}
__device__ __forceinline__ uint32_t pack_rn(float lo, float hi) {
    uint32_t r;
    asm("cvt.rn.satfinite.bf16x2.f32 %0, %1, %2;" : "=r"(r) : "f"(hi), "f"(lo));
    return r;
}
__device__ __forceinline__ uint32_t pack_hi16(float lo, float hi) {
    return __byte_perm(__float_as_uint(lo), __float_as_uint(hi), 0x7632);
}
__device__ __forceinline__ float trunc_bf(float v) {
    return __uint_as_float(__float_as_uint(v) & 0xFFFF0000u);
}
__device__ __forceinline__ float rn_bf(float v) {
    return __bfloat162float(__float2bfloat16(v));
}

__global__ __launch_bounds__(THREADS)
void sdfvae_mma_kernel(const float* __restrict__ points,
                       const float* __restrict__ features,
                       const float* __restrict__ W0,
                       const float* __restrict__ W1,
                       const float* __restrict__ W2,
                       const float* __restrict__ W3,
                       float* __restrict__ out)
{
    const int chunk = blockIdx.x, p = blockIdx.y, b = blockIdx.z;
    const int tid = threadIdx.x;
    const int w = tid >> 5, lane = tid & 31;
    const int g = lane >> 2, q = lane & 3;

    __shared__ uint32_t sPEh[4][32][9];
    __shared__ uint32_t sPEm[4][32][9];

    // B fragments in registers (built once from gmem)
    uint32_t b0h[4][2], b0m[4][2];
    uint32_t b1h[4][2][2], b1m[4][2][2];
    uint32_t b2h[4][2][2], b2m[4][2][2];
    float    w3r[4][2];

    const float* W0p = W0 + p * 32 * 17;
    const float* fv  = features + (b * P_ + p) * 8;

    #pragma unroll
    for (int j = 0; j < 4; j++) {
        const int n = g + 8 * j;
        const float* w0r = W0p + n * 17;
        float bias = 0.f;
        #pragma unroll
        for (int t = 0; t < 8; t++) bias = fmaf(fv[t], w0r[9 + t], bias);

        float v0 = w0r[2 * q], v1 = w0r[2 * q + 1];
        b0h[j][0] = pack_rn(rn_bf(v0), rn_bf(v1));
        b0m[j][0] = pack_rn(v0 - rn_bf(v0), v1 - rn_bf(v1));
        if (q == 0) {
            float u0 = w0r[8], u1 = bias;
            b0h[j][1] = pack_rn(rn_bf(u0), rn_bf(u1));
            b0m[j][1] = pack_rn(u0 - rn_bf(u0), u1 - rn_bf(u1));
        } else {
            b0h[j][1] = 0u; b0m[j][1] = 0u;
        }

        const float* w1r = W1 + p * 1024 + n * 32;
        const float* w2r = W2 + p * 1024 + n * 32;
        #pragma unroll
        for (int kb = 0; kb < 2; kb++) {
            int k0 = 2 * q + 16 * kb;
            float a0 = w1r[k0], a1 = w1r[k0 + 1], a2 = w1r[k0 + 8], a3 = w1r[k0 + 9];
            b1h[j][kb][0] = pack_rn(rn_bf(a0), rn_bf(a1));
            b1m[j][kb][0] = pack_rn(a0 - rn_bf(a0), a1 - rn_bf(a1));
            b1h[j][kb][1] = pack_rn(rn_bf(a2), rn_bf(a3));
            b1m[j][kb][1] = pack_rn(a2 - rn_bf(a2), a3 - rn_bf(a3));
            float c0 = w2r[k0], c1 = w2r[k0 + 1], c2 = w2r[k0 + 8], c3 = w2r[k0 + 9];
            b2h[j][kb][0] = pack_rn(rn_bf(c0), rn_bf(c1));
            b2m[j][kb][0] = pack_rn(c0 - rn_bf(c0), c1 - rn_bf(c1));
            b2h[j][kb][1] = pack_rn(rn_bf(c2), rn_bf(c3));
            b2m[j][kb][1] = pack_rn(c2 - rn_bf(c2), c3 - rn_bf(c3));
        }
        w3r[j][0] = W3[p * 32 + 8 * j + 2 * q];
        w3r[j][1] = W3[p * 32 + 8 * j + 2 * q + 1];
    }

    const long long pbase = (long long)(b * P_ + p) * N_ + (long long)chunk * CHUNK;
    const long long obase = (long long)b * N_ + (long long)chunk * CHUNK;

    // ---- prefetch iteration 0's point ----
    float nx, ny, nz;
    {
        const float* pt = points + (pbase + w * 32 + lane) * 3;
        nx = __ldg(pt); ny = __ldg(pt + 1); nz = __ldg(pt + 2);
    }

    for (int it = 0; it < ITERS; it++) {
        const int mwarp = it * 128 + w * 32;

        const float x = nx, y = ny, z = nz;

        // ---- prefetch next iteration's point (clamped on last iter) ----
        {
            const int itn = (it + 1 < ITERS) ? it + 1 : it;
            const float* pt = points + (pbase + itn * 128 + w * 32 + lane) * 3;
            nx = __ldg(pt); ny = __ldg(pt + 1); nz = __ldg(pt + 2);
        }

        __syncwarp();
        {
            float v[10];
            v[0] = x; v[1] = y; v[2] = z;
            __sincosf(x, &v[3], &v[6]);
            __sincosf(y, &v[4], &v[7]);
            __sincosf(z, &v[5], &v[8]);
            v[9] = 1.f;
            #pragma unroll
            for (int t = 0; t < 5; t++) {
                float a = v[2 * t], c = v[2 * t + 1];
                sPEh[w][lane][t] = pack_rn(rn_bf(a), rn_bf(c));
                sPEm[w][lane][t] = pack_rn(a - rn_bf(a), c - rn_bf(c));
            }
            #pragma unroll
            for (int t = 5; t < 8; t++) {
                sPEh[w][lane][t] = 0u;
                sPEm[w][lane][t] = 0u;
            }
        }
        __syncwarp();

        // ---- fused processing of both 16-row tiles ----
        uint32_t A0h[2][4], A0m[2][4];
        #pragma unroll
        for (int t = 0; t < 2; t++) {
            const int rb = t * 16;
            A0h[t][0] = sPEh[w][rb + g][q];
            A0h[t][1] = sPEh[w][rb + g + 8][q];
            A0h[t][2] = sPEh[w][rb + g][q + 4];
            A0h[t][3] = sPEh[w][rb + g + 8][q + 4];
            A0m[t][0] = sPEm[w][rb + g][q];
            A0m[t][1] = sPEm[w][rb + g + 8][q];
            A0m[t][2] = sPEm[w][rb + g][q + 4];
            A0m[t][3] = sPEm[w][rb + g + 8][q + 4];
        }

        float C[2][4][4];
        #pragma unroll
        for (int t = 0; t < 2; t++)
            #pragma unroll
            for (int n = 0; n < 4; n++)
                C[t][n][0] = C[t][n][1] = C[t][n][2] = C[t][n][3] = 0.f;

        // ---- L0 (K=16): 3 terms x 2 tiles x 4 n = 24 MMAs ----
        #pragma unroll
        for (int t = 0; t < 2; t++)
            #pragma unroll
            for (int n = 0; n < 4; n++) {
                mma16816(C[t][n], A0h[t], b0h[n][0], b0h[n][1]);
                mma16816(C[t][n], A0m[t], b0h[n][0], b0h[n][1]);
                mma16816(C[t][n], A0h[t], b0m[n][0], b0m[n][1]);
            }

        uint32_t Ah[2][2][4], Am[2][2][4];
        #pragma unroll
        for (int t = 0; t < 2; t++)
            #pragma unroll
            for (int n = 0; n < 4; n++) {
                float c0 = fmaxf(C[t][n][0], 0.f), c1 = fmaxf(C[t][n][1], 0.f);
                float c2 = fmaxf(C[t][n][2], 0.f), c3 = fmaxf(C[t][n][3], 0.f);
                int kb = n >> 1, pos = (n & 1) * 2;
                Ah[t][kb][pos]     = pack_hi16(c0, c1);
                Ah[t][kb][pos + 1] = pack_hi16(c2, c3);
                Am[t][kb][pos]     = pack_hi16(c0 - trunc_bf(c0), c1 - trunc_bf(c1));
                Am[t][kb][pos + 1] = pack_hi16(c2 - trunc_bf(c2), c3 - trunc_bf(c3));
            }

        // ---- L1 (K=32): 48 MMAs ----
        #pragma unroll
        for (int t = 0; t < 2; t++)
            #pragma unroll
            for (int n = 0; n < 4; n++)
                C[t][n][0] = C[t][n][1] = C[t][n][2] = C[t][n][3] = 0.f;
        #pragma unroll
        for (int t = 0; t < 2; t++)
            #pragma unroll
            for (int n = 0; n < 4; n++)
                #pragma unroll
                for (int kb = 0; kb < 2; kb++) {
                    mma16816(C[t][n], Ah[t][kb], b1h[n][kb][0], b1h[n][kb][1]);
                    mma16816(C[t][n], Am[t][kb], b1h[n][kb][0], b1h[n][kb][1]);
                    mma16816(C[t][n], Ah[t][kb], b1m[n][kb][0], b1m[n][kb][1]);
                }
        #pragma unroll
        for (int t = 0; t < 2; t++)
            #pragma unroll
            for (int n = 0; n < 4; n++) {
                float c0 = fmaxf(C[t][n][0], 0.f), c1 = fmaxf(C[t][n][1], 0.f);
                float c2 = fmaxf(C[t][n][2], 0.f), c3 = fmaxf(C[t][n][3], 0.f);
                int kb = n >> 1, pos = (n & 1) * 2;
                Ah[t][kb][pos]     = pack_hi16(c0, c1);
                Ah[t][kb][pos + 1] = pack_hi16(c2, c3);
                Am[t][kb][pos]     = pack_hi16(c0 - trunc_bf(c0), c1 - trunc_bf(c1));
                Am[t][kb][pos + 1] = pack_hi16(c2 - trunc_bf(c2), c3 - trunc_bf(c3));
            }

        // ---- L2 (K=32): 48 MMAs ----
        #pragma unroll
        for (int t = 0; t < 2; t++)
            #pragma unroll
            for (int n = 0; n < 4; n++)
                C[t][n][0] = C[t][n][1] = C[t][n][2] = C[t][n][3] = 0.f;
        #pragma unroll
        for (int t = 0; t < 2; t++)
            #pragma unroll
            for (int n = 0; n < 4; n++)
                #pragma unroll
                for (int kb = 0; kb < 2; kb++) {
                    mma16816(C[t][n], Ah[t][kb], b2h[n][kb][0], b2h[n][kb][1]);
                    mma16816(C[t][n], Am[t][kb], b2h[n][kb][0], b2h[n][kb][1]);
                    mma16816(C[t][n], Ah[t][kb], b2m[n][kb][0], b2m[n][kb][1]);
                }

        // ---- L3: relu + per-thread dot + butterfly over q-group ----
        #pragma unroll
        for (int t = 0; t < 2; t++) {
            float s0 = 0.f, s1 = 0.f;
            #pragma unroll
            for (int n = 0; n < 4; n++) {
                s0 = fmaf(fmaxf(C[t][n][0], 0.f), w3r[n][0], s0);
                s0 = fmaf(fmaxf(C[t][n][1], 0.f), w3r[n][1], s0);
                s1 = fmaf(fmaxf(C[t][n][2], 0.f), w3r[n][0], s1);
                s1 = fmaf(fmaxf(C[t][n][3], 0.f), w3r[n][1], s1);
            }
            s0 += __shfl_xor_sync(0xFFFFFFFFu, s0, 1);
            s0 += __shfl_xor_sync(0xFFFFFFFFu, s0, 2);
            s1 += __shfl_xor_sync(0xFFFFFFFFu, s1, 1);
            s1 += __shfl_xor_sync(0xFFFFFFFFu, s1, 2);
            if (q == 0) {
                long long m0 = obase + mwarp + t * 16 + g;
                out[m0 * P_ + p]       = s0;
                out[(m0 + 8) * P_ + p] = s1;
            }
        }
    }
}

extern "C" void kernel_launch(void* const* d_in, const int* in_sizes, int n_in,
                              void* d_out, int out_size)
{
    const float* points   = (const float*)d_in[0];
    const float* features = (const float*)d_in[1];
    const float* W0       = (const float*)d_in[2];
    const float* W1       = (const float*)d_in[3];
    const float* W2       = (const float*)d_in[4];
    const float* W3       = (const float*)d_in[5];
    float* out = (float*)d_out;

    dim3 grid(N_ / CHUNK, P_, B_);
    sdfvae_mma_kernel<<<grid, THREADS>>>(points, features, W0, W1, W2, W3, out);
}

// round 14
// speedup vs baseline: 1.6493x; 1.4922x over previous
#include <cuda_runtime.h>
#include <cuda_fp16.h>
#include <cstdint>

// SDFVae per-part MLP on mma.sync.m16n8k16 (fp16, weights split hi+mid,
// f32 accum). R14: 2-term scheme — A rounded to fp16 once, weights carry the
// precision as fp16 hi+mid (one-time prep). 80 MMAs/warp-iter vs 120.
// Error: dropped (A-Ah)*B term ~2^-12 RMS/layer -> rel_err ~2-5e-4.
//   d_in[0] points [8,42,16384,3] f32   d_in[1] features [8,336] f32
//   d_in[2] W0 [42,32,17]  d_in[3] W1 [42,32,32]
//   d_in[4] W2 [42,32,32]  d_in[5] W3 [42,1,32]
//   out [8,16384,42] f32

#define B_ 8
#define P_ 42
#define N_ 16384
#define THREADS 128
#define CHUNK 2048
#define ITERS (CHUNK / 128)   // 16

__device__ __forceinline__ void mma_f16(float c[4],
    const uint32_t a[4], uint32_t b0, uint32_t b1)
{
    asm volatile(
        "mma.sync.aligned.m16n8k16.row.col.f32.f16.f16.f32 "
        "{%0,%1,%2,%3}, {%4,%5,%6,%7}, {%8,%9}, {%0,%1,%2,%3};"
        : "+f"(c[0]), "+f"(c[1]), "+f"(c[2]), "+f"(c[3])
        : "r"(a[0]), "r"(a[1]), "r"(a[2]), "r"(a[3]), "r"(b0), "r"(b1));
}
// f16x2 {lo,hi} from two f32 (round-to-nearest)
__device__ __forceinline__ uint32_t pack_f16(float lo, float hi) {
    uint32_t r;
    asm("cvt.rn.f16x2.f32 %0, %1, %2;" : "=r"(r) : "f"(hi), "f"(lo));
    return r;
}
__device__ __forceinline__ float h16(float v) {
    return __half2float(__float2half_rn(v));
}

__global__ __launch_bounds__(THREADS)
void sdfvae_mma_kernel(const float* __restrict__ points,
                       const float* __restrict__ features,
                       const float* __restrict__ W0,
                       const float* __restrict__ W1,
                       const float* __restrict__ W2,
                       const float* __restrict__ W3,
                       float* __restrict__ out)
{
    const int chunk = blockIdx.x, p = blockIdx.y, b = blockIdx.z;
    const int tid = threadIdx.x;
    const int w = tid >> 5, lane = tid & 31;
    const int g = lane >> 2, q = lane & 3;

    __shared__ uint32_t sPE[4][32][9];   // fp16x2 pe pairs (pairs 0..7, pad 9)

    // Weight fragments, fp16 hi+mid (built once from gmem)
    uint32_t b0h[4][2], b0m[4][2];         // L0  [ntile][b0,b1]
    uint32_t b1h[4][2][2], b1m[4][2][2];   // L1  [ntile][kb][b0,b1]
    uint32_t b2h[4][2][2], b2m[4][2][2];   // L2
    float    w3r[4][2];

    const float* W0p = W0 + p * 32 * 17;
    const float* fv  = features + (b * P_ + p) * 8;

    #pragma unroll
    for (int j = 0; j < 4; j++) {
        const int n = g + 8 * j;
        const float* w0r = W0p + n * 17;
        float bias = 0.f;
        #pragma unroll
        for (int t = 0; t < 8; t++) bias = fmaf(fv[t], w0r[9 + t], bias);

        // L0 b0: k = 2q, 2q+1 (always real pe cols)
        float v0 = w0r[2 * q], v1 = w0r[2 * q + 1];
        b0h[j][0] = pack_f16(h16(v0), h16(v1));
        b0m[j][0] = pack_f16(v0 - h16(v0), v1 - h16(v1));
        // L0 b1: k = 2q+8, 2q+9 : q==0 -> (W0[.,8], bias); q>0 -> zero
        if (q == 0) {
            float u0 = w0r[8], u1 = bias;
            b0h[j][1] = pack_f16(h16(u0), h16(u1));
            b0m[j][1] = pack_f16(u0 - h16(u0), u1 - h16(u1));
        } else {
            b0h[j][1] = 0u; b0m[j][1] = 0u;
        }

        const float* w1r = W1 + p * 1024 + n * 32;
        const float* w2r = W2 + p * 1024 + n * 32;
        #pragma unroll
        for (int kb = 0; kb < 2; kb++) {
            int k0 = 2 * q + 16 * kb;
            float a0 = w1r[k0], a1 = w1r[k0 + 1], a2 = w1r[k0 + 8], a3 = w1r[k0 + 9];
            b1h[j][kb][0] = pack_f16(h16(a0), h16(a1));
            b1m[j][kb][0] = pack_f16(a0 - h16(a0), a1 - h16(a1));
            b1h[j][kb][1] = pack_f16(h16(a2), h16(a3));
            b1m[j][kb][1] = pack_f16(a2 - h16(a2), a3 - h16(a3));
            float c0 = w2r[k0], c1 = w2r[k0 + 1], c2 = w2r[k0 + 8], c3 = w2r[k0 + 9];
            b2h[j][kb][0] = pack_f16(h16(c0), h16(c1));
            b2m[j][kb][0] = pack_f16(c0 - h16(c0), c1 - h16(c1));
            b2h[j][kb][1] = pack_f16(h16(c2), h16(c3));
            b2m[j][kb][1] = pack_f16(c2 - h16(c2), c3 - h16(c3));
        }
        w3r[j][0] = W3[p * 32 + 8 * j + 2 * q];
        w3r[j][1] = W3[p * 32 + 8 * j + 2 * q + 1];
    }

    const long long pbase = (long long)(b * P_ + p) * N_ + (long long)chunk * CHUNK;
    const long long obase = (long long)b * N_ + (long long)chunk * CHUNK;

    // ---- prefetch iteration 0's point ----
    float nx, ny, nz;
    {
        const float* pt = points + (pbase + w * 32 + lane) * 3;
        nx = __ldg(pt); ny = __ldg(pt + 1); nz = __ldg(pt + 2);
    }

    for (int it = 0; it < ITERS; it++) {
        const int mwarp = it * 128 + w * 32;

        const float x = nx, y = ny, z = nz;

        // prefetch next iteration's point (clamped on last iter)
        {
            const int itn = (it + 1 < ITERS) ? it + 1 : it;
            const float* pt = points + (pbase + itn * 128 + w * 32 + lane) * 3;
            nx = __ldg(pt); ny = __ldg(pt + 1); nz = __ldg(pt + 2);
        }

        __syncwarp();
        {
            float v[10];
            v[0] = x; v[1] = y; v[2] = z;
            __sincosf(x, &v[3], &v[6]);
            __sincosf(y, &v[4], &v[7]);
            __sincosf(z, &v[5], &v[8]);
            v[9] = 1.f;
            #pragma unroll
            for (int t = 0; t < 5; t++)
                sPE[w][lane][t] = pack_f16(v[2 * t], v[2 * t + 1]);
            #pragma unroll
            for (int t = 5; t < 8; t++)
                sPE[w][lane][t] = 0u;
        }
        __syncwarp();

        // ---- A0 fragments (fp16, single version) ----
        uint32_t A0[2][4];
        #pragma unroll
        for (int t = 0; t < 2; t++) {
            const int rb = t * 16;
            A0[t][0] = sPE[w][rb + g][q];
            A0[t][1] = sPE[w][rb + g + 8][q];
            A0[t][2] = sPE[w][rb + g][q + 4];
            A0[t][3] = sPE[w][rb + g + 8][q + 4];
        }

        float C[2][4][4];
        #pragma unroll
        for (int t = 0; t < 2; t++)
            #pragma unroll
            for (int n = 0; n < 4; n++)
                C[t][n][0] = C[t][n][1] = C[t][n][2] = C[t][n][3] = 0.f;

        // ---- L0 (K=16): 2 terms x 2 tiles x 4 n = 16 MMAs ----
        #pragma unroll
        for (int t = 0; t < 2; t++)
            #pragma unroll
            for (int n = 0; n < 4; n++) {
                mma_f16(C[t][n], A0[t], b0h[n][0], b0h[n][1]);
                mma_f16(C[t][n], A0[t], b0m[n][0], b0m[n][1]);
            }

        // transition: relu + single fp16 pack (no residual)
        uint32_t Ah[2][2][4];
        #pragma unroll
        for (int t = 0; t < 2; t++)
            #pragma unroll
            for (int n = 0; n < 4; n++) {
                float c0 = fmaxf(C[t][n][0], 0.f), c1 = fmaxf(C[t][n][1], 0.f);
                float c2 = fmaxf(C[t][n][2], 0.f), c3 = fmaxf(C[t][n][3], 0.f);
                int kb = n >> 1, pos = (n & 1) * 2;
                Ah[t][kb][pos]     = pack_f16(c0, c1);
                Ah[t][kb][pos + 1] = pack_f16(c2, c3);
            }

        // ---- L1 (K=32): 2 terms x 2 kb x 4 n x 2 tiles = 32 MMAs ----
        #pragma unroll
        for (int t = 0; t < 2; t++)
            #pragma unroll
            for (int n = 0; n < 4; n++)
                C[t][n][0] = C[t][n][1] = C[t][n][2] = C[t][n][3] = 0.f;
        #pragma unroll
        for (int t = 0; t < 2; t++)
            #pragma unroll
            for (int n = 0; n < 4; n++)
                #pragma unroll
                for (int kb = 0; kb < 2; kb++) {
                    mma_f16(C[t][n], Ah[t][kb], b1h[n][kb][0], b1h[n][kb][1]);
                    mma_f16(C[t][n], Ah[t][kb], b1m[n][kb][0], b1m[n][kb][1]);
                }
        #pragma unroll
        for (int t = 0; t < 2; t++)
            #pragma unroll
            for (int n = 0; n < 4; n++) {
                float c0 = fmaxf(C[t][n][0], 0.f), c1 = fmaxf(C[t][n][1], 0.f);
                float c2 = fmaxf(C[t][n][2], 0.f), c3 = fmaxf(C[t][n][3], 0.f);
                int kb = n >> 1, pos = (n & 1) * 2;
                Ah[t][kb][pos]     = pack_f16(c0, c1);
                Ah[t][kb][pos + 1] = pack_f16(c2, c3);
            }

        // ---- L2 (K=32): 32 MMAs ----
        #pragma unroll
        for (int t = 0; t < 2; t++)
            #pragma unroll
            for (int n = 0; n < 4; n++)
                C[t][n][0] = C[t][n][1] = C[t][n][2] = C[t][n][3] = 0.f;
        #pragma unroll
        for (int t = 0; t < 2; t++)
            #pragma unroll
            for (int n = 0; n < 4; n++)
                #pragma unroll
                for (int kb = 0; kb < 2; kb++) {
                    mma_f16(C[t][n], Ah[t][kb], b2h[n][kb][0], b2h[n][kb][1]);
                    mma_f16(C[t][n], Ah[t][kb], b2m[n][kb][0], b2m[n][kb][1]);
                }

        // ---- L3: relu + per-thread f32 dot + butterfly over q-group ----
        #pragma unroll
        for (int t = 0; t < 2; t++) {
            float s0 = 0.f, s1 = 0.f;
            #pragma unroll
            for (int n = 0; n < 4; n++) {
                s0 = fmaf(fmaxf(C[t][n][0], 0.f), w3r[n][0], s0);
                s0 = fmaf(fmaxf(C[t][n][1], 0.f), w3r[n][1], s0);
                s1 = fmaf(fmaxf(C[t][n][2], 0.f), w3r[n][0], s1);
                s1 = fmaf(fmaxf(C[t][n][3], 0.f), w3r[n][1], s1);
            }
            s0 += __shfl_xor_sync(0xFFFFFFFFu, s0, 1);
            s0 += __shfl_xor_sync(0xFFFFFFFFu, s0, 2);
            s1 += __shfl_xor_sync(0xFFFFFFFFu, s1, 1);
            s1 += __shfl_xor_sync(0xFFFFFFFFu, s1, 2);
            if (q == 0) {
                long long m0 = obase + mwarp + t * 16 + g;
                out[m0 * P_ + p]       = s0;
                out[(m0 + 8) * P_ + p] = s1;
            }
        }
    }
}

extern "C" void kernel_launch(void* const* d_in, const int* in_sizes, int n_in,
                              void* d_out, int out_size)
{
    const float* points   = (const float*)d_in[0];
    const float* features = (const float*)d_in[1];
    const float* W0       = (const float*)d_in[2];
    const float* W1       = (const float*)d_in[3];
    const float* W2       = (const float*)d_in[4];
    const float* W3       = (const float*)d_in[5];
    float* out = (float*)d_out;

    dim3 grid(N_ / CHUNK, P_, B_);
    sdfvae_mma_kernel<<<grid, THREADS>>>(points, features, W0, W1, W2, W3, out);
}

// round 16
// speedup vs baseline: 2.5187x; 1.5272x over previous
#include <cuda_runtime.h>
#include <cuda_fp16.h>
#include <cstdint>

// SDFVae per-part MLP on mma.sync.m16n8k16 (pure fp16 operands, f32 accum).
// R16 = R15 resubmit (infra failure): single-term MMAs — fp16 products
// accumulate exactly in f32, so the only error is operand rounding
// (~2^-12 per side per layer). 40 MMAs/iter vs 80. Expected rel_err ~5e-4.
//   d_in[0] points [8,42,16384,3] f32   d_in[1] features [8,336] f32
//   d_in[2] W0 [42,32,17]  d_in[3] W1 [42,32,32]
//   d_in[4] W2 [42,32,32]  d_in[5] W3 [42,1,32]
//   out [8,16384,42] f32

#define B_ 8
#define P_ 42
#define N_ 16384
#define THREADS 128
#define CHUNK 2048
#define ITERS (CHUNK / 128)   // 16

__device__ __forceinline__ void mma_f16(float c[4],
    const uint32_t a[4], uint32_t b0, uint32_t b1)
{
    asm volatile(
        "mma.sync.aligned.m16n8k16.row.col.f32.f16.f16.f32 "
        "{%0,%1,%2,%3}, {%4,%5,%6,%7}, {%8,%9}, {%0,%1,%2,%3};"
        : "+f"(c[0]), "+f"(c[1]), "+f"(c[2]), "+f"(c[3])
        : "r"(a[0]), "r"(a[1]), "r"(a[2]), "r"(a[3]), "r"(b0), "r"(b1));
}
__device__ __forceinline__ uint32_t pack_f16(float lo, float hi) {
    uint32_t r;
    asm("cvt.rn.f16x2.f32 %0, %1, %2;" : "=r"(r) : "f"(hi), "f"(lo));
    return r;
}

__global__ __launch_bounds__(THREADS)
void sdfvae_mma_kernel(const float* __restrict__ points,
                       const float* __restrict__ features,
                       const float* __restrict__ W0,
                       const float* __restrict__ W1,
                       const float* __restrict__ W2,
                       const float* __restrict__ W3,
                       float* __restrict__ out)
{
    const int chunk = blockIdx.x, p = blockIdx.y, b = blockIdx.z;
    const int tid = threadIdx.x;
    const int w = tid >> 5, lane = tid & 31;
    const int g = lane >> 2, q = lane & 3;

    __shared__ uint32_t sPE[4][32][9];   // fp16x2 pe pairs (pairs 0..7, pad 9)

    // fp16 weight fragments (built once from gmem)
    uint32_t b0f[4][2];        // L0 [ntile][b0,b1]
    uint32_t b1f[4][2][2];     // L1 [ntile][kb][b0,b1]
    uint32_t b2f[4][2][2];     // L2
    float    w3r[4][2];

    const float* W0p = W0 + p * 32 * 17;
    const float* fv  = features + (b * P_ + p) * 8;

    #pragma unroll
    for (int j = 0; j < 4; j++) {
        const int n = g + 8 * j;
        const float* w0r = W0p + n * 17;
        float bias = 0.f;
        #pragma unroll
        for (int t = 0; t < 8; t++) bias = fmaf(fv[t], w0r[9 + t], bias);

        b0f[j][0] = pack_f16(w0r[2 * q], w0r[2 * q + 1]);
        b0f[j][1] = (q == 0) ? pack_f16(w0r[8], bias) : 0u;

        const float* w1r = W1 + p * 1024 + n * 32;
        const float* w2r = W2 + p * 1024 + n * 32;
        #pragma unroll
        for (int kb = 0; kb < 2; kb++) {
            int k0 = 2 * q + 16 * kb;
            b1f[j][kb][0] = pack_f16(w1r[k0], w1r[k0 + 1]);
            b1f[j][kb][1] = pack_f16(w1r[k0 + 8], w1r[k0 + 9]);
            b2f[j][kb][0] = pack_f16(w2r[k0], w2r[k0 + 1]);
            b2f[j][kb][1] = pack_f16(w2r[k0 + 8], w2r[k0 + 9]);
        }
        w3r[j][0] = W3[p * 32 + 8 * j + 2 * q];
        w3r[j][1] = W3[p * 32 + 8 * j + 2 * q + 1];
    }

    const long long pbase = (long long)(b * P_ + p) * N_ + (long long)chunk * CHUNK;
    const long long obase = (long long)b * N_ + (long long)chunk * CHUNK;

    // prefetch iteration 0's point
    float nx, ny, nz;
    {
        const float* pt = points + (pbase + w * 32 + lane) * 3;
        nx = __ldg(pt); ny = __ldg(pt + 1); nz = __ldg(pt + 2);
    }

    for (int it = 0; it < ITERS; it++) {
        const int mwarp = it * 128 + w * 32;

        const float x = nx, y = ny, z = nz;
        {
            const int itn = (it + 1 < ITERS) ? it + 1 : it;
            const float* pt = points + (pbase + itn * 128 + w * 32 + lane) * 3;
            nx = __ldg(pt); ny = __ldg(pt + 1); nz = __ldg(pt + 2);
        }

        __syncwarp();
        {
            float v[10];
            v[0] = x; v[1] = y; v[2] = z;
            __sincosf(x, &v[3], &v[6]);
            __sincosf(y, &v[4], &v[7]);
            __sincosf(z, &v[5], &v[8]);
            v[9] = 1.f;
            #pragma unroll
            for (int t = 0; t < 5; t++)
                sPE[w][lane][t] = pack_f16(v[2 * t], v[2 * t + 1]);
            #pragma unroll
            for (int t = 5; t < 8; t++)
                sPE[w][lane][t] = 0u;
        }
        __syncwarp();

        uint32_t A0[2][4];
        #pragma unroll
        for (int t = 0; t < 2; t++) {
            const int rb = t * 16;
            A0[t][0] = sPE[w][rb + g][q];
            A0[t][1] = sPE[w][rb + g + 8][q];
            A0[t][2] = sPE[w][rb + g][q + 4];
            A0[t][3] = sPE[w][rb + g + 8][q + 4];
        }

        float C[2][4][4];
        #pragma unroll
        for (int t = 0; t < 2; t++)
            #pragma unroll
            for (int n = 0; n < 4; n++)
                C[t][n][0] = C[t][n][1] = C[t][n][2] = C[t][n][3] = 0.f;

        // ---- L0 (K=16): 2 tiles x 4 n = 8 MMAs ----
        #pragma unroll
        for (int t = 0; t < 2; t++)
            #pragma unroll
            for (int n = 0; n < 4; n++)
                mma_f16(C[t][n], A0[t], b0f[n][0], b0f[n][1]);

        uint32_t Ah[2][2][4];
        #pragma unroll
        for (int t = 0; t < 2; t++)
            #pragma unroll
            for (int n = 0; n < 4; n++) {
                float c0 = fmaxf(C[t][n][0], 0.f), c1 = fmaxf(C[t][n][1], 0.f);
                float c2 = fmaxf(C[t][n][2], 0.f), c3 = fmaxf(C[t][n][3], 0.f);
                int kb = n >> 1, pos = (n & 1) * 2;
                Ah[t][kb][pos]     = pack_f16(c0, c1);
                Ah[t][kb][pos + 1] = pack_f16(c2, c3);
            }

        // ---- L1 (K=32): 2 tiles x 4 n x 2 kb = 16 MMAs ----
        #pragma unroll
        for (int t = 0; t < 2; t++)
            #pragma unroll
            for (int n = 0; n < 4; n++)
                C[t][n][0] = C[t][n][1] = C[t][n][2] = C[t][n][3] = 0.f;
        #pragma unroll
        for (int t = 0; t < 2; t++)
            #pragma unroll
            for (int n = 0; n < 4; n++)
                #pragma unroll
                for (int kb = 0; kb < 2; kb++)
                    mma_f16(C[t][n], Ah[t][kb], b1f[n][kb][0], b1f[n][kb][1]);
        #pragma unroll
        for (int t = 0; t < 2; t++)
            #pragma unroll
            for (int n = 0; n < 4; n++) {
                float c0 = fmaxf(C[t][n][0], 0.f), c1 = fmaxf(C[t][n][1], 0.f);
                float c2 = fmaxf(C[t][n][2], 0.f), c3 = fmaxf(C[t][n][3], 0.f);
                int kb = n >> 1, pos = (n & 1) * 2;
                Ah[t][kb][pos]     = pack_f16(c0, c1);
                Ah[t][kb][pos + 1] = pack_f16(c2, c3);
            }

        // ---- L2 (K=32): 16 MMAs ----
        #pragma unroll
        for (int t = 0; t < 2; t++)
            #pragma unroll
            for (int n = 0; n < 4; n++)
                C[t][n][0] = C[t][n][1] = C[t][n][2] = C[t][n][3] = 0.f;
        #pragma unroll
        for (int t = 0; t < 2; t++)
            #pragma unroll
            for (int n = 0; n < 4; n++)
                #pragma unroll
                for (int kb = 0; kb < 2; kb++)
                    mma_f16(C[t][n], Ah[t][kb], b2f[n][kb][0], b2f[n][kb][1]);

        // ---- L3: relu + per-thread f32 dot + butterfly over q-group ----
        #pragma unroll
        for (int t = 0; t < 2; t++) {
            float s0 = 0.f, s1 = 0.f;
            #pragma unroll
            for (int n = 0; n < 4; n++) {
                s0 = fmaf(fmaxf(C[t][n][0], 0.f), w3r[n][0], s0);
                s0 = fmaf(fmaxf(C[t][n][1], 0.f), w3r[n][1], s0);
                s1 = fmaf(fmaxf(C[t][n][2], 0.f), w3r[n][0], s1);
                s1 = fmaf(fmaxf(C[t][n][3], 0.f), w3r[n][1], s1);
            }
            s0 += __shfl_xor_sync(0xFFFFFFFFu, s0, 1);
            s0 += __shfl_xor_sync(0xFFFFFFFFu, s0, 2);
            s1 += __shfl_xor_sync(0xFFFFFFFFu, s1, 1);
            s1 += __shfl_xor_sync(0xFFFFFFFFu, s1, 2);
            if (q == 0) {
                long long m0 = obase + mwarp + t * 16 + g;
                out[m0 * P_ + p]       = s0;
                out[(m0 + 8) * P_ + p] = s1;
            }
        }
    }
}

extern "C" void kernel_launch(void* const* d_in, const int* in_sizes, int n_in,
                              void* d_out, int out_size)
{
    const float* points   = (const float*)d_in[0];
    const float* features = (const float*)d_in[1];
    const float* W0       = (const float*)d_in[2];
    const float* W1       = (const float*)d_in[3];
    const float* W2       = (const float*)d_in[4];
    const float* W3       = (const float*)d_in[5];
    float* out = (float*)d_out;

    dim3 grid(N_ / CHUNK, P_, B_);
    sdfvae_mma_kernel<<<grid, THREADS>>>(points, features, W0, W1, W2, W3, out);
}

// round 17
// speedup vs baseline: 2.5203x; 1.0006x over previous
#include <cuda_runtime.h>
#include <cuda_fp16.h>
#include <cstdint>

// SDFVae per-part MLP on mma.sync.m16n8k16 (pure fp16 operands, f32 accum).
// R17 = R16 + two exact ALU cuts: (1) zero-input-C MMA variant removes all
// accumulator-zeroing MOVs; (2) relu fused into f16 domain via max.f16x2
// after packing (max(cvt(x),0) == cvt(max(x,0))). ~30% fewer issue slots.
//   d_in[0] points [8,42,16384,3] f32   d_in[1] features [8,336] f32
//   d_in[2] W0 [42,32,17]  d_in[3] W1 [42,32,32]
//   d_in[4] W2 [42,32,32]  d_in[5] W3 [42,1,32]
//   out [8,16384,42] f32

#define B_ 8
#define P_ 42
#define N_ 16384
#define THREADS 128
#define CHUNK 2048
#define ITERS (CHUNK / 128)   // 16

__device__ __forceinline__ void mma_f16(float c[4],
    const uint32_t a[4], uint32_t b0, uint32_t b1)
{
    asm volatile(
        "mma.sync.aligned.m16n8k16.row.col.f32.f16.f16.f32 "
        "{%0,%1,%2,%3}, {%4,%5,%6,%7}, {%8,%9}, {%0,%1,%2,%3};"
        : "+f"(c[0]), "+f"(c[1]), "+f"(c[2]), "+f"(c[3])
        : "r"(a[0]), "r"(a[1]), "r"(a[2]), "r"(a[3]), "r"(b0), "r"(b1));
}
// first MMA of a chain: input C is a zero register, D written directly
__device__ __forceinline__ void mma_f16_zero(float c[4],
    const uint32_t a[4], uint32_t b0, uint32_t b1)
{
    asm volatile(
        "mma.sync.aligned.m16n8k16.row.col.f32.f16.f16.f32 "
        "{%0,%1,%2,%3}, {%4,%5,%6,%7}, {%8,%9}, {%10,%10,%10,%10};"
        : "=f"(c[0]), "=f"(c[1]), "=f"(c[2]), "=f"(c[3])
        : "r"(a[0]), "r"(a[1]), "r"(a[2]), "r"(a[3]), "r"(b0), "r"(b1),
          "f"(0.f));
}
__device__ __forceinline__ uint32_t pack_f16(float lo, float hi) {
    uint32_t r;
    asm("cvt.rn.f16x2.f32 %0, %1, %2;" : "=r"(r) : "f"(hi), "f"(lo));
    return r;
}
// relu on a packed f16x2 pair (one instruction)
__device__ __forceinline__ uint32_t relu2(uint32_t v) {
    uint32_t r;
    asm("max.f16x2 %0, %1, %2;" : "=r"(r) : "r"(v), "r"(0u));
    return r;
}

__global__ __launch_bounds__(THREADS)
void sdfvae_mma_kernel(const float* __restrict__ points,
                       const float* __restrict__ features,
                       const float* __restrict__ W0,
                       const float* __restrict__ W1,
                       const float* __restrict__ W2,
                       const float* __restrict__ W3,
                       float* __restrict__ out)
{
    const int chunk = blockIdx.x, p = blockIdx.y, b = blockIdx.z;
    const int tid = threadIdx.x;
    const int w = tid >> 5, lane = tid & 31;
    const int g = lane >> 2, q = lane & 3;

    __shared__ uint32_t sPE[4][32][9];   // fp16x2 pe pairs (pairs 0..7, pad 9)

    // fp16 weight fragments (built once from gmem)
    uint32_t b0f[4][2];        // L0 [ntile][b0,b1]
    uint32_t b1f[4][2][2];     // L1 [ntile][kb][b0,b1]
    uint32_t b2f[4][2][2];     // L2
    float    w3r[4][2];

    const float* W0p = W0 + p * 32 * 17;
    const float* fv  = features + (b * P_ + p) * 8;

    #pragma unroll
    for (int j = 0; j < 4; j++) {
        const int n = g + 8 * j;
        const float* w0r = W0p + n * 17;
        float bias = 0.f;
        #pragma unroll
        for (int t = 0; t < 8; t++) bias = fmaf(fv[t], w0r[9 + t], bias);

        b0f[j][0] = pack_f16(w0r[2 * q], w0r[2 * q + 1]);
        b0f[j][1] = (q == 0) ? pack_f16(w0r[8], bias) : 0u;

        const float* w1r = W1 + p * 1024 + n * 32;
        const float* w2r = W2 + p * 1024 + n * 32;
        #pragma unroll
        for (int kb = 0; kb < 2; kb++) {
            int k0 = 2 * q + 16 * kb;
            b1f[j][kb][0] = pack_f16(w1r[k0], w1r[k0 + 1]);
            b1f[j][kb][1] = pack_f16(w1r[k0 + 8], w1r[k0 + 9]);
            b2f[j][kb][0] = pack_f16(w2r[k0], w2r[k0 + 1]);
            b2f[j][kb][1] = pack_f16(w2r[k0 + 8], w2r[k0 + 9]);
        }
        w3r[j][0] = W3[p * 32 + 8 * j + 2 * q];
        w3r[j][1] = W3[p * 32 + 8 * j + 2 * q + 1];
    }

    const long long pbase = (long long)(b * P_ + p) * N_ + (long long)chunk * CHUNK;
    const long long obase = (long long)b * N_ + (long long)chunk * CHUNK;

    // prefetch iteration 0's point
    float nx, ny, nz;
    {
        const float* pt = points + (pbase + w * 32 + lane) * 3;
        nx = __ldg(pt); ny = __ldg(pt + 1); nz = __ldg(pt + 2);
    }

    for (int it = 0; it < ITERS; it++) {
        const int mwarp = it * 128 + w * 32;

        const float x = nx, y = ny, z = nz;
        {
            const int itn = (it + 1 < ITERS) ? it + 1 : it;
            const float* pt = points + (pbase + itn * 128 + w * 32 + lane) * 3;
            nx = __ldg(pt); ny = __ldg(pt + 1); nz = __ldg(pt + 2);
        }

        __syncwarp();
        {
            float v[10];
            v[0] = x; v[1] = y; v[2] = z;
            __sincosf(x, &v[3], &v[6]);
            __sincosf(y, &v[4], &v[7]);
            __sincosf(z, &v[5], &v[8]);
            v[9] = 1.f;
            #pragma unroll
            for (int t = 0; t < 5; t++)
                sPE[w][lane][t] = pack_f16(v[2 * t], v[2 * t + 1]);
            #pragma unroll
            for (int t = 5; t < 8; t++)
                sPE[w][lane][t] = 0u;
        }
        __syncwarp();

        uint32_t A0[2][4];
        #pragma unroll
        for (int t = 0; t < 2; t++) {
            const int rb = t * 16;
            A0[t][0] = sPE[w][rb + g][q];
            A0[t][1] = sPE[w][rb + g + 8][q];
            A0[t][2] = sPE[w][rb + g][q + 4];
            A0[t][3] = sPE[w][rb + g + 8][q + 4];
        }

        float C[2][4][4];

        // ---- L0 (K=16): 8 MMAs, zero-C variant (no accumulator init) ----
        #pragma unroll
        for (int t = 0; t < 2; t++)
            #pragma unroll
            for (int n = 0; n < 4; n++)
                mma_f16_zero(C[t][n], A0[t], b0f[n][0], b0f[n][1]);

        // transition: pack then relu in f16 domain (exact)
        uint32_t Ah[2][2][4];
        #pragma unroll
        for (int t = 0; t < 2; t++)
            #pragma unroll
            for (int n = 0; n < 4; n++) {
                int kb = n >> 1, pos = (n & 1) * 2;
                Ah[t][kb][pos]     = relu2(pack_f16(C[t][n][0], C[t][n][1]));
                Ah[t][kb][pos + 1] = relu2(pack_f16(C[t][n][2], C[t][n][3]));
            }

        // ---- L1 (K=32): 16 MMAs (kb=0 zero-C, kb=1 accumulate) ----
        #pragma unroll
        for (int t = 0; t < 2; t++)
            #pragma unroll
            for (int n = 0; n < 4; n++) {
                mma_f16_zero(C[t][n], Ah[t][0], b1f[n][0][0], b1f[n][0][1]);
                mma_f16(C[t][n], Ah[t][1], b1f[n][1][0], b1f[n][1][1]);
            }
        #pragma unroll
        for (int t = 0; t < 2; t++)
            #pragma unroll
            for (int n = 0; n < 4; n++) {
                int kb = n >> 1, pos = (n & 1) * 2;
                Ah[t][kb][pos]     = relu2(pack_f16(C[t][n][0], C[t][n][1]));
                Ah[t][kb][pos + 1] = relu2(pack_f16(C[t][n][2], C[t][n][3]));
            }

        // ---- L2 (K=32): 16 MMAs ----
        #pragma unroll
        for (int t = 0; t < 2; t++)
            #pragma unroll
            for (int n = 0; n < 4; n++) {
                mma_f16_zero(C[t][n], Ah[t][0], b2f[n][0][0], b2f[n][0][1]);
                mma_f16(C[t][n], Ah[t][1], b2f[n][1][0], b2f[n][1][1]);
            }

        // ---- L3: relu + per-thread f32 dot + butterfly over q-group ----
        #pragma unroll
        for (int t = 0; t < 2; t++) {
            float s0 = 0.f, s1 = 0.f;
            #pragma unroll
            for (int n = 0; n < 4; n++) {
                s0 = fmaf(fmaxf(C[t][n][0], 0.f), w3r[n][0], s0);
                s0 = fmaf(fmaxf(C[t][n][1], 0.f), w3r[n][1], s0);
                s1 = fmaf(fmaxf(C[t][n][2], 0.f), w3r[n][0], s1);
                s1 = fmaf(fmaxf(C[t][n][3], 0.f), w3r[n][1], s1);
            }
            s0 += __shfl_xor_sync(0xFFFFFFFFu, s0, 1);
            s0 += __shfl_xor_sync(0xFFFFFFFFu, s0, 2);
            s1 += __shfl_xor_sync(0xFFFFFFFFu, s1, 1);
            s1 += __shfl_xor_sync(0xFFFFFFFFu, s1, 2);
            if (q == 0) {
                long long m0 = obase + mwarp + t * 16 + g;
                out[m0 * P_ + p]       = s0;
                out[(m0 + 8) * P_ + p] = s1;
            }
        }
    }
}

extern "C" void kernel_launch(void* const* d_in, const int* in_sizes, int n_in,
                              void* d_out, int out_size)
{
    const float* points   = (const float*)d_in[0];
    const float* features = (const float*)d_in[1];
    const float* W0       = (const float*)d_in[2];
    const float* W1       = (const float*)d_in[3];
    const float* W2       = (const float*)d_in[4];
    const float* W3       = (const float*)d_in[5];
    float* out = (float*)d_out;

    dim3 grid(N_ / CHUNK, P_, B_);
    sdfvae_mma_kernel<<<grid, THREADS>>>(points, features, W0, W1, W2, W3, out);
}